// round 6
// baseline (speedup 1.0000x reference)
#include <cuda_runtime.h>
#include <math.h>

typedef unsigned long long ull;

#define BB 128
#define TT 512
#define IND 64
#define HD 256
#define G3 768
#define LD 32
#define NPARD 1056
#define ODD 8

#define CL 4            // cluster size (K split of hidden dim)
#define NBAT 4          // batches per cluster
#define KS (HD/CL)      // 64 K-columns per CTA

// Scratch (static device arrays — no allocation allowed)
__device__ float g_gx[BB*TT*G3];        // 192 MB
__device__ float g_rnn[BB*TT*HD];       // 64 MB
__device__ float g_te[BB*TT*LD];        // 8 MB
__device__ float g_par[(size_t)BB*TT*NPARD]; // 277 MB

__device__ __forceinline__ float sigm(float x){ return 1.0f/(1.0f+expf(-x)); }

// packed fp32 FMA (Blackwell f32x2) and horizontal add
__device__ __forceinline__ ull fma2(ull a, ull b, ull c){
    ull d;
    asm("fma.rn.f32x2 %0, %1, %2, %3;" : "=l"(d) : "l"(a), "l"(b), "l"(c));
    return d;
}
__device__ __forceinline__ float hadd2(ull a){
    unsigned lo, hi;
    asm("mov.b64 {%0,%1}, %2;" : "=r"(lo), "=r"(hi) : "l"(a));
    return __uint_as_float(lo) + __uint_as_float(hi);
}

// ------------------------------------------------------------------
// K1: gx[bt,g] = x[bt,:] . w_ih[g,:] + b_ih[g]   (f32x2 microkernel)
// ------------------------------------------------------------------
__global__ __launch_bounds__(256) void k_gx(const float* __restrict__ x,
                                            const float* __restrict__ w_ih,
                                            const float* __restrict__ b_ih)
{
    __shared__ float2 xs[64][33];
    __shared__ float2 ws[64][33];
    int m0 = blockIdx.y * 64;
    int n0 = blockIdx.x * 64;
    int tid = threadIdx.y * 16 + threadIdx.x;
    const float4* x4 = (const float4*)x;
    const float4* w4 = (const float4*)w_ih;
    for (int q = tid; q < 1024; q += 256) {
        int row = q >> 4, c4 = q & 15;
        float4 v = x4[(size_t)(m0 + row) * 16 + c4];
        xs[row][c4*2+0] = make_float2(v.x, v.y);
        xs[row][c4*2+1] = make_float2(v.z, v.w);
        float4 wv = w4[(size_t)(n0 + row) * 16 + c4];
        ws[row][c4*2+0] = make_float2(wv.x, wv.y);
        ws[row][c4*2+1] = make_float2(wv.z, wv.w);
    }
    __syncthreads();
    int tr = threadIdx.y * 4, tc = threadIdx.x * 4;
    ull acc[4][4] = {};
    #pragma unroll 8
    for (int k2 = 0; k2 < 32; k2++) {
        ull av[4], bv[4];
        #pragma unroll
        for (int i = 0; i < 4; i++) av[i] = *(const ull*)&xs[tr + i][k2];
        #pragma unroll
        for (int j = 0; j < 4; j++) bv[j] = *(const ull*)&ws[tc + j][k2];
        #pragma unroll
        for (int i = 0; i < 4; i++)
            #pragma unroll
            for (int j = 0; j < 4; j++)
                acc[i][j] = fma2(av[i], bv[j], acc[i][j]);
    }
    float b0 = b_ih[n0+tc+0], b1 = b_ih[n0+tc+1], b2 = b_ih[n0+tc+2], b3 = b_ih[n0+tc+3];
    #pragma unroll
    for (int i = 0; i < 4; i++) {
        float4 o;
        o.x = hadd2(acc[i][0]) + b0; o.y = hadd2(acc[i][1]) + b1;
        o.z = hadd2(acc[i][2]) + b2; o.w = hadd2(acc[i][3]) + b3;
        *(float4*)&g_gx[(size_t)(m0 + tr + i) * G3 + n0 + tc] = o;
    }
}

// ------------------------------------------------------------------
// K2: GRU recurrence, cluster of 4 CTAs (K split).
// w_hh slice split: low 32 K in REGISTERS (fits RF), high 32 K in SMEM.
// ------------------------------------------------------------------
#define GRU_WS_SMEM (G3 * 36 * 4)   // 768 rows x 36-word pitch
__global__ __launch_bounds__(G3, 1) __cluster_dims__(CL, 1, 1)
void k_gru(const float* __restrict__ hidden,
           const float* __restrict__ w_hh,
           const float* __restrict__ b_hh,
           float* __restrict__ hT)
{
    extern __shared__ float ws_dyn[];           // [768][36] pitch, hi half of w
    __shared__ float4 hs4[NBAT][KS/4];          // local hidden slice, 4 x 64
    __shared__ float pbuf[2][CL][NBAT][192];    // partial sums, double-buffered
    int tid = threadIdx.x;
    unsigned rank;
    asm("mov.u32 %0, %%cluster_ctarank;" : "=r"(rank));
    int b0 = (blockIdx.x / CL) * NBAT;

    // w slice: row = tid, k in [KS*rank, KS*rank+64)
    // low 32 floats -> registers; high 32 floats -> smem row
    float4 w_lo[8];
    {
        const float4* wsrc = (const float4*)(w_hh + (size_t)tid * HD + KS * rank);
        #pragma unroll
        for (int i = 0; i < 8; i++) w_lo[i] = wsrc[i];
        float4* wrow = (float4*)&ws_dyn[tid * 36];
        #pragma unroll
        for (int i = 0; i < 8; i++) wrow[i] = wsrc[8 + i];
    }

    float* hs = (float*)hs4;
    int gb = tid >> 6, gj = tid & 63;           // gate-thread coords (tid<256)
    int hidx = KS * (int)rank + gj;
    float bh_r = 0.f, bh_z = 0.f, bh_n = 0.f;
    if (tid < NBAT * KS) {
        hs[gb * KS + gj] = hidden[(size_t)(b0 + gb) * HD + hidx];
        bh_r = b_hh[hidx]; bh_z = b_hh[HD + hidx]; bh_n = b_hh[2*HD + hidx];
    }

    // partial routing: row r=tid -> dest CTA=(r&255)>>6, slot=(r>>8)*64+(r&63)
    int dest = (tid & 255) >> 6;
    int slot = (tid >> 8) * 64 + (tid & 63);
    unsigned raddr0, raddr1;
    {
        unsigned la0 = (unsigned)__cvta_generic_to_shared(&pbuf[0][rank][0][slot]);
        unsigned la1 = (unsigned)__cvta_generic_to_shared(&pbuf[1][rank][0][slot]);
        asm("mapa.shared::cluster.u32 %0, %1, %2;" : "=r"(raddr0) : "r"(la0), "r"(dest));
        asm("mapa.shared::cluster.u32 %0, %1, %2;" : "=r"(raddr1) : "r"(la1), "r"(dest));
    }
    __syncthreads();

    const float4* wrow_hi = (const float4*)&ws_dyn[tid * 36];

    for (int t = 0; t < TT; t++) {
        // prefetch gx (long-scoreboard covered by FMA block below)
        float xr = 0.f, xz = 0.f, xn = 0.f;
        if (tid < NBAT * KS) {
            const float* gxp = g_gx + ((size_t)(b0 + gb) * TT + t) * G3;
            xr = gxp[hidx]; xz = gxp[HD + hidx]; xn = gxp[2*HD + hidx];
        }
        // partial gh for 4 batches over local K slice (f32x2)
        ull a0 = 0ull, a1 = 0ull, a2 = 0ull, a3 = 0ull;
        #pragma unroll
        for (int k = 0; k < 8; k++) {       // low half: w in regs
            float4 wv = w_lo[k];
            ull w01 = *(const ull*)&wv.x;
            ull w23 = *(const ull*)&wv.z;
            float4 h0 = hs4[0][k];
            a0 = fma2(w01, *(const ull*)&h0.x, a0);
            a0 = fma2(w23, *(const ull*)&h0.z, a0);
            float4 h1 = hs4[1][k];
            a1 = fma2(w01, *(const ull*)&h1.x, a1);
            a1 = fma2(w23, *(const ull*)&h1.z, a1);
            float4 h2 = hs4[2][k];
            a2 = fma2(w01, *(const ull*)&h2.x, a2);
            a2 = fma2(w23, *(const ull*)&h2.z, a2);
            float4 h3 = hs4[3][k];
            a3 = fma2(w01, *(const ull*)&h3.x, a3);
            a3 = fma2(w23, *(const ull*)&h3.z, a3);
        }
        #pragma unroll
        for (int k = 0; k < 8; k++) {       // high half: w from smem
            float4 wv = wrow_hi[k];
            ull w01 = *(const ull*)&wv.x;
            ull w23 = *(const ull*)&wv.z;
            float4 h0 = hs4[0][8 + k];
            a0 = fma2(w01, *(const ull*)&h0.x, a0);
            a0 = fma2(w23, *(const ull*)&h0.z, a0);
            float4 h1 = hs4[1][8 + k];
            a1 = fma2(w01, *(const ull*)&h1.x, a1);
            a1 = fma2(w23, *(const ull*)&h1.z, a1);
            float4 h2 = hs4[2][8 + k];
            a2 = fma2(w01, *(const ull*)&h2.x, a2);
            a2 = fma2(w23, *(const ull*)&h2.z, a2);
            float4 h3 = hs4[3][8 + k];
            a3 = fma2(w01, *(const ull*)&h3.x, a3);
            a3 = fma2(w23, *(const ull*)&h3.z, a3);
        }
        float s0 = hadd2(a0), s1 = hadd2(a1), s2 = hadd2(a2), s3 = hadd2(a3);

        // ship partials to owning CTA (batch stride = 192 floats = 768 B)
        unsigned ra = (t & 1) ? raddr1 : raddr0;
        asm volatile("st.shared::cluster.f32 [%0], %1;" :: "r"(ra),         "f"(s0));
        asm volatile("st.shared::cluster.f32 [%0], %1;" :: "r"(ra + 768u),  "f"(s1));
        asm volatile("st.shared::cluster.f32 [%0], %1;" :: "r"(ra + 1536u), "f"(s2));
        asm volatile("st.shared::cluster.f32 [%0], %1;" :: "r"(ra + 2304u), "f"(s3));
        asm volatile("barrier.cluster.arrive.aligned;" ::: "memory");
        asm volatile("barrier.cluster.wait.aligned;"   ::: "memory");

        // gate phase: combine 4 partials per gate, update local h slice
        if (tid < NBAT * KS) {
            int buf = t & 1;
            float hr = pbuf[buf][0][gb][gj]     + pbuf[buf][1][gb][gj]
                     + pbuf[buf][2][gb][gj]     + pbuf[buf][3][gb][gj]     + bh_r;
            float hz = pbuf[buf][0][gb][64+gj]  + pbuf[buf][1][gb][64+gj]
                     + pbuf[buf][2][gb][64+gj]  + pbuf[buf][3][gb][64+gj]  + bh_z;
            float hn = pbuf[buf][0][gb][128+gj] + pbuf[buf][1][gb][128+gj]
                     + pbuf[buf][2][gb][128+gj] + pbuf[buf][3][gb][128+gj] + bh_n;
            float r = sigm(xr + hr);
            float z = sigm(xz + hz);
            float n = tanhf(xn + r * hn);
            float hp = hs[gb*KS + gj];
            float hnew = (1.0f - z) * n + z * hp;
            hs[gb*KS + gj] = hnew;
            g_rnn[((size_t)(b0 + gb) * TT + t) * HD + hidx] = hnew;
        }
        __syncthreads();
    }
    if (tid < NBAT * KS) hT[(size_t)(b0 + gb) * HD + hidx] = hs[gb*KS + gj];
}

// ------------------------------------------------------------------
// K3a: task_enc[bt,l] = rnn[bt,:] . w_lat[l,:] + b_lat[l]  (f32x2)
// ------------------------------------------------------------------
__global__ __launch_bounds__(256) void k_te(const float* __restrict__ w_lat,
                                            const float* __restrict__ b_lat)
{
    __shared__ ulonglong2 rows4[32 * 64];
    int tid = threadIdx.x;
    int bt0 = blockIdx.x * 32;
    const ulonglong2* rnn4 = (const ulonglong2*)g_rnn;
    for (int q = tid; q < 2048; q += 256) rows4[q] = rnn4[(size_t)bt0 * 64 + q];
    __syncthreads();
    int pair = tid >> 3;
    int l0 = (tid & 7) * 4;
    const ulonglong2* wl4 = (const ulonglong2*)w_lat;
    ull acc[4] = {};
    #pragma unroll 8
    for (int k4 = 0; k4 < 64; k4++) {
        ulonglong2 r = rows4[pair * 64 + k4];
        #pragma unroll
        for (int j = 0; j < 4; j++) {
            ulonglong2 wv = wl4[(size_t)(l0 + j) * 64 + k4];
            acc[j] = fma2(r.x, wv.x, acc[j]);
            acc[j] = fma2(r.y, wv.y, acc[j]);
        }
    }
    float4 o;
    o.x = hadd2(acc[0]) + b_lat[l0+0];
    o.y = hadd2(acc[1]) + b_lat[l0+1];
    o.z = hadd2(acc[2]) + b_lat[l0+2];
    o.w = hadd2(acc[3]) + b_lat[l0+3];
    *(float4*)&g_te[(size_t)(bt0 + pair) * LD + l0] = o;
}

// ------------------------------------------------------------------
// K4: params GEMM: g_par[bt][idx] = b_par[idx] + w_par[idx,:] . te[bt,:]
// tile 96 idx x 64 bt, K=32; block 16x16, microtile 6 idx x 4 bt.
// ------------------------------------------------------------------
__global__ __launch_bounds__(256) void k_par(const float* __restrict__ w_par,
                                             const float* __restrict__ b_par)
{
    __shared__ float ws_s[96][36];
    __shared__ float te_s[64][36];
    __shared__ float bp_s[96];
    int idx0 = blockIdx.x * 96;
    int bt0  = blockIdx.y * 64;
    int tx = threadIdx.x, ty = threadIdx.y;
    int tid = ty * 16 + tx;

    // load w tile: 96 rows x 32 floats = 768 float4
    for (int q = tid; q < 768; q += 256) {
        int row = q >> 3, c4 = q & 7;
        float4 v = ((const float4*)w_par)[(size_t)(idx0 + row) * 8 + c4];
        *(float4*)&ws_s[row][c4 * 4] = v;
    }
    // load te tile: 64 rows x 32 floats = 512 float4
    for (int q = tid; q < 512; q += 256) {
        int row = q >> 3, c4 = q & 7;
        float4 v = ((const float4*)g_te)[(size_t)(bt0 + row) * 8 + c4];
        *(float4*)&te_s[row][c4 * 4] = v;
    }
    if (tid < 96) bp_s[tid] = b_par[idx0 + tid];
    __syncthreads();

    int ix = tx * 6;      // idx offset (6 outputs)
    int ib = ty * 4;      // bt offset (4 outputs)
    ull acc[4][6] = {};
    #pragma unroll
    for (int k2 = 0; k2 < 16; k2++) {
        ull av[6], bv[4];
        #pragma unroll
        for (int i = 0; i < 6; i++) av[i] = *(const ull*)&ws_s[ix + i][k2 * 2];
        #pragma unroll
        for (int j = 0; j < 4; j++) bv[j] = *(const ull*)&te_s[ib + j][k2 * 2];
        #pragma unroll
        for (int j = 0; j < 4; j++)
            #pragma unroll
            for (int i = 0; i < 6; i++)
                acc[j][i] = fma2(av[i], bv[j], acc[j][i]);
    }
    #pragma unroll
    for (int j = 0; j < 4; j++) {
        float* orow = g_par + (size_t)(bt0 + ib + j) * NPARD + idx0 + ix;
        #pragma unroll
        for (int i = 0; i < 6; i++) orow[i] = hadd2(acc[j][i]) + bp_s[ix + i];
    }
}

// ------------------------------------------------------------------
// K5: head — per bt read params row + states, do hyper-MLP.
// ------------------------------------------------------------------
#define PAIRS 8
__global__ __launch_bounds__(256) void k_head(const float* __restrict__ x,
                                              float* __restrict__ out_mean,
                                              float* __restrict__ out_std)
{
    __shared__ float ps[PAIRS * NPARD];    // 33.8 KB
    __shared__ float st_s[PAIRS][48];
    __shared__ float hid[PAIRS][16];
    int tid = threadIdx.x;
    int bt0 = blockIdx.x * PAIRS;

    // coalesced copy of 8 param rows (8448 floats = 2112 float4)
    {
        const float4* src = (const float4*)(g_par + (size_t)bt0 * NPARD);
        float4* dst = (float4*)ps;
        for (int q = tid; q < PAIRS * (NPARD/4); q += 256) dst[q] = src[q];
    }
    if (tid < PAIRS * 12) {
        int p = tid / 12, c = tid % 12;
        ((float4*)&st_s[p][0])[c] = ((const float4*)x)[(size_t)(bt0 + p) * 16 + c];
    }
    __syncthreads();

    // phase 2: out_hidden[pair][p] = tanh(w_h[p,:] . state + b_h[p])
    if (tid < PAIRS * 16) {
        int pair = tid >> 4, p = tid & 15;
        const float4* wh4 = (const float4*)(ps + pair * NPARD + p * 48);
        const float4* st4 = (const float4*)&st_s[pair][0];
        float a = ps[pair * NPARD + 768 + p];
        #pragma unroll
        for (int q = 0; q < 12; q++) {
            float4 wv = wh4[q];
            float4 sv = st4[q];
            a = fmaf(wv.x, sv.x, a); a = fmaf(wv.y, sv.y, a);
            a = fmaf(wv.z, sv.z, a); a = fmaf(wv.w, sv.w, a);
        }
        hid[pair][p] = tanhf(a);
    }
    __syncthreads();

    // phase 3: mlp[pair][o] = w_o[o,:] . hidden + b_o[o]
    if (tid < PAIRS * 16) {
        int pair = tid >> 4, o = tid & 15;
        const float4* wo4 = (const float4*)(ps + pair * NPARD + 784 + o * 16);
        const float4* hv4 = (const float4*)&hid[pair][0];
        float m = ps[pair * NPARD + 1040 + o];
        #pragma unroll
        for (int q = 0; q < 4; q++) {
            float4 wv = wo4[q];
            float4 hv = hv4[q];
            m = fmaf(wv.x, hv.x, m); m = fmaf(wv.y, hv.y, m);
            m = fmaf(wv.z, hv.z, m); m = fmaf(wv.w, hv.w, m);
        }
        size_t bt = bt0 + pair;
        if (o < 8) out_mean[bt * ODD + o] = m;
        else       out_std[bt * ODD + (o - 8)] = expf(m);
    }
}

// ------------------------------------------------------------------
extern "C" void kernel_launch(void* const* d_in, const int* in_sizes, int n_in,
                              void* d_out, int out_size)
{
    const float* x      = (const float*)d_in[0];
    const float* hidden = (const float*)d_in[1];
    const float* w_ih   = (const float*)d_in[2];
    const float* w_hh   = (const float*)d_in[3];
    const float* b_ih   = (const float*)d_in[4];
    const float* b_hh   = (const float*)d_in[5];
    const float* w_lat  = (const float*)d_in[6];
    const float* b_lat  = (const float*)d_in[7];
    const float* w_par  = (const float*)d_in[8];
    const float* b_par  = (const float*)d_in[9];
    (void)in_sizes; (void)n_in; (void)out_size;

    float* out      = (float*)d_out;
    float* out_mean = out;                                  // B*T*8
    float* out_std  = out + (size_t)BB * TT * ODD;          // B*T*8
    float* out_hT   = out + (size_t)2 * BB * TT * ODD;      // B*256

    cudaFuncSetAttribute(k_gru, cudaFuncAttributeMaxDynamicSharedMemorySize, GRU_WS_SMEM);

    dim3 g1(G3 / 64, (BB * TT) / 64), b1(16, 16);
    k_gx  <<<g1, b1>>>(x, w_ih, b_ih);
    k_gru <<<(BB / NBAT) * CL, G3, GRU_WS_SMEM>>>(hidden, w_hh, b_hh, out_hT);
    k_te  <<<(BB * TT) / 32, 256>>>(w_lat, b_lat);
    dim3 g4(NPARD / 96, (BB * TT) / 64), b4(16, 16);
    k_par <<<g4, b4>>>(w_par, b_par);
    k_head<<<(BB * TT) / PAIRS, 256>>>(x, out_mean, out_std);
}

// round 9
// speedup vs baseline: 1.4524x; 1.4524x over previous
#include <cuda_runtime.h>
#include <math.h>

typedef unsigned long long ull;

#define BB 128
#define TT 512
#define IND 64
#define HD 256
#define G3 768
#define LD 32
#define NPARD 1056
#define ODD 8

#define CL 4            // cluster size (K split of hidden dim)
#define NBAT 4          // batches per cluster
#define KS (HD/CL)      // 64 K-columns per CTA

// Scratch (static device arrays — no allocation allowed)
__device__ float g_gx[BB*TT*G3];    // 192 MB
__device__ float g_rnn[BB*TT*HD];   // 64 MB
__device__ float g_te[BB*TT*LD];    // 8 MB

__device__ __forceinline__ float sigm(float x){ return 1.0f/(1.0f+expf(-x)); }

// packed fp32 ops (Blackwell f32x2)
__device__ __forceinline__ ull fma2(ull a, ull b, ull c){
    ull d;
    asm("fma.rn.f32x2 %0, %1, %2, %3;" : "=l"(d) : "l"(a), "l"(b), "l"(c));
    return d;
}
__device__ __forceinline__ ull add2(ull a, ull b){
    ull d;
    asm("add.rn.f32x2 %0, %1, %2;" : "=l"(d) : "l"(a), "l"(b));
    return d;
}
__device__ __forceinline__ float hadd2(ull a){
    unsigned lo, hi;
    asm("mov.b64 {%0,%1}, %2;" : "=r"(lo), "=r"(hi) : "l"(a));
    return __uint_as_float(lo) + __uint_as_float(hi);
}

// ------------------------------------------------------------------
// K1: gx[bt,g] = x[bt,:] . w_ih[g,:] + b_ih[g]   (f32x2 microkernel)
// ------------------------------------------------------------------
__global__ __launch_bounds__(256) void k_gx(const float* __restrict__ x,
                                            const float* __restrict__ w_ih,
                                            const float* __restrict__ b_ih)
{
    __shared__ float2 xs[64][33];
    __shared__ float2 ws[64][33];
    int m0 = blockIdx.y * 64;
    int n0 = blockIdx.x * 64;
    int tid = threadIdx.y * 16 + threadIdx.x;
    const float4* x4 = (const float4*)x;
    const float4* w4 = (const float4*)w_ih;
    for (int q = tid; q < 1024; q += 256) {
        int row = q >> 4, c4 = q & 15;
        float4 v = x4[(size_t)(m0 + row) * 16 + c4];
        xs[row][c4*2+0] = make_float2(v.x, v.y);
        xs[row][c4*2+1] = make_float2(v.z, v.w);
        float4 wv = w4[(size_t)(n0 + row) * 16 + c4];
        ws[row][c4*2+0] = make_float2(wv.x, wv.y);
        ws[row][c4*2+1] = make_float2(wv.z, wv.w);
    }
    __syncthreads();
    int tr = threadIdx.y * 4, tc = threadIdx.x * 4;
    ull acc[4][4] = {};
    #pragma unroll 8
    for (int k2 = 0; k2 < 32; k2++) {
        ull av[4], bv[4];
        #pragma unroll
        for (int i = 0; i < 4; i++) av[i] = *(const ull*)&xs[tr + i][k2];
        #pragma unroll
        for (int j = 0; j < 4; j++) bv[j] = *(const ull*)&ws[tc + j][k2];
        #pragma unroll
        for (int i = 0; i < 4; i++)
            #pragma unroll
            for (int j = 0; j < 4; j++)
                acc[i][j] = fma2(av[i], bv[j], acc[i][j]);
    }
    float b0 = b_ih[n0+tc+0], b1 = b_ih[n0+tc+1], b2 = b_ih[n0+tc+2], b3 = b_ih[n0+tc+3];
    #pragma unroll
    for (int i = 0; i < 4; i++) {
        float4 o;
        o.x = hadd2(acc[i][0]) + b0; o.y = hadd2(acc[i][1]) + b1;
        o.z = hadd2(acc[i][2]) + b2; o.w = hadd2(acc[i][3]) + b3;
        *(float4*)&g_gx[(size_t)(m0 + tr + i) * G3 + n0 + tc] = o;
    }
}

// ------------------------------------------------------------------
// K2: GRU recurrence (R5 version, best measured): cluster of 4 CTAs,
// w_hh in registers, f32x2 FMA, h via LDS.128.
// ------------------------------------------------------------------
__global__ __launch_bounds__(G3, 1) __cluster_dims__(CL, 1, 1)
void k_gru(const float* __restrict__ hidden,
           const float* __restrict__ w_hh,
           const float* __restrict__ b_hh,
           float* __restrict__ hT)
{
    __shared__ float4 hs4[NBAT][KS/4];          // local hidden slice, 4 x 64
    __shared__ float pbuf[2][CL][NBAT][192];    // partial sums, double-buffered
    int tid = threadIdx.x;
    unsigned rank;
    asm("mov.u32 %0, %%cluster_ctarank;" : "=r"(rank));
    int b0 = (blockIdx.x / CL) * NBAT;

    float4 w[KS/4];
    {
        const float4* wsrc = (const float4*)(w_hh + (size_t)tid * HD + KS * rank);
        #pragma unroll
        for (int i = 0; i < KS/4; i++) w[i] = wsrc[i];
    }

    float* hs = (float*)hs4;
    int gb = tid >> 6, gj = tid & 63;
    int hidx = KS * (int)rank + gj;
    float bh_r = 0.f, bh_z = 0.f, bh_n = 0.f;
    if (tid < NBAT * KS) {
        hs[gb * KS + gj] = hidden[(size_t)(b0 + gb) * HD + hidx];
        bh_r = b_hh[hidx]; bh_z = b_hh[HD + hidx]; bh_n = b_hh[2*HD + hidx];
    }

    int dest = (tid & 255) >> 6;
    int slot = (tid >> 8) * 64 + (tid & 63);
    unsigned raddr0, raddr1;
    {
        unsigned la0 = (unsigned)__cvta_generic_to_shared(&pbuf[0][rank][0][slot]);
        unsigned la1 = (unsigned)__cvta_generic_to_shared(&pbuf[1][rank][0][slot]);
        asm("mapa.shared::cluster.u32 %0, %1, %2;" : "=r"(raddr0) : "r"(la0), "r"(dest));
        asm("mapa.shared::cluster.u32 %0, %1, %2;" : "=r"(raddr1) : "r"(la1), "r"(dest));
    }
    __syncthreads();

    for (int t = 0; t < TT; t++) {
        float xr = 0.f, xz = 0.f, xn = 0.f;
        if (tid < NBAT * KS) {
            const float* gxp = g_gx + ((size_t)(b0 + gb) * TT + t) * G3;
            xr = gxp[hidx]; xz = gxp[HD + hidx]; xn = gxp[2*HD + hidx];
        }
        ull a0 = 0ull, a1 = 0ull, a2 = 0ull, a3 = 0ull;
        #pragma unroll
        for (int k = 0; k < KS/4; k++) {
            float4 wv = w[k];
            ull w01 = *(const ull*)&wv.x;
            ull w23 = *(const ull*)&wv.z;
            float4 h0 = hs4[0][k];
            a0 = fma2(w01, *(const ull*)&h0.x, a0);
            a0 = fma2(w23, *(const ull*)&h0.z, a0);
            float4 h1 = hs4[1][k];
            a1 = fma2(w01, *(const ull*)&h1.x, a1);
            a1 = fma2(w23, *(const ull*)&h1.z, a1);
            float4 h2 = hs4[2][k];
            a2 = fma2(w01, *(const ull*)&h2.x, a2);
            a2 = fma2(w23, *(const ull*)&h2.z, a2);
            float4 h3 = hs4[3][k];
            a3 = fma2(w01, *(const ull*)&h3.x, a3);
            a3 = fma2(w23, *(const ull*)&h3.z, a3);
        }
        float s0 = hadd2(a0), s1 = hadd2(a1), s2 = hadd2(a2), s3 = hadd2(a3);

        unsigned ra = (t & 1) ? raddr1 : raddr0;
        asm volatile("st.shared::cluster.f32 [%0], %1;" :: "r"(ra),         "f"(s0));
        asm volatile("st.shared::cluster.f32 [%0], %1;" :: "r"(ra + 768u),  "f"(s1));
        asm volatile("st.shared::cluster.f32 [%0], %1;" :: "r"(ra + 1536u), "f"(s2));
        asm volatile("st.shared::cluster.f32 [%0], %1;" :: "r"(ra + 2304u), "f"(s3));
        asm volatile("barrier.cluster.arrive.aligned;" ::: "memory");
        asm volatile("barrier.cluster.wait.aligned;"   ::: "memory");

        if (tid < NBAT * KS) {
            int buf = t & 1;
            float hr = pbuf[buf][0][gb][gj]     + pbuf[buf][1][gb][gj]
                     + pbuf[buf][2][gb][gj]     + pbuf[buf][3][gb][gj]     + bh_r;
            float hz = pbuf[buf][0][gb][64+gj]  + pbuf[buf][1][gb][64+gj]
                     + pbuf[buf][2][gb][64+gj]  + pbuf[buf][3][gb][64+gj]  + bh_z;
            float hn = pbuf[buf][0][gb][128+gj] + pbuf[buf][1][gb][128+gj]
                     + pbuf[buf][2][gb][128+gj] + pbuf[buf][3][gb][128+gj] + bh_n;
            float r = sigm(xr + hr);
            float z = sigm(xz + hz);
            float n = tanhf(xn + r * hn);
            float hp = hs[gb*KS + gj];
            float hnew = (1.0f - z) * n + z * hp;
            hs[gb*KS + gj] = hnew;
            g_rnn[((size_t)(b0 + gb) * TT + t) * HD + hidx] = hnew;
        }
        __syncthreads();
    }
    if (tid < NBAT * KS) hT[(size_t)(b0 + gb) * HD + hidx] = hs[gb*KS + gj];
}

// ------------------------------------------------------------------
// K3a: task_enc[bt,l] = rnn[bt,:] . w_lat[l,:] + b_lat[l]  (f32x2)
// ------------------------------------------------------------------
__global__ __launch_bounds__(256) void k_te(const float* __restrict__ w_lat,
                                            const float* __restrict__ b_lat)
{
    __shared__ ulonglong2 rows4[32 * 64];
    int tid = threadIdx.x;
    int bt0 = blockIdx.x * 32;
    const ulonglong2* rnn4 = (const ulonglong2*)g_rnn;
    for (int q = tid; q < 2048; q += 256) rows4[q] = rnn4[(size_t)bt0 * 64 + q];
    __syncthreads();
    int pair = tid >> 3;
    int l0 = (tid & 7) * 4;
    const ulonglong2* wl4 = (const ulonglong2*)w_lat;
    ull acc[4] = {};
    #pragma unroll 8
    for (int k4 = 0; k4 < 64; k4++) {
        ulonglong2 r = rows4[pair * 64 + k4];
        #pragma unroll
        for (int j = 0; j < 4; j++) {
            ulonglong2 wv = wl4[(size_t)(l0 + j) * 64 + k4];
            acc[j] = fma2(r.x, wv.x, acc[j]);
            acc[j] = fma2(r.y, wv.y, acc[j]);
        }
    }
    float4 o;
    o.x = hadd2(acc[0]) + b_lat[l0+0];
    o.y = hadd2(acc[1]) + b_lat[l0+1];
    o.z = hadd2(acc[2]) + b_lat[l0+2];
    o.w = hadd2(acc[3]) + b_lat[l0+3];
    *(float4*)&g_te[(size_t)(bt0 + pair) * LD + l0] = o;
}

// ------------------------------------------------------------------
// K3b: fused tail, warp-per-pair. 512 threads = 16 warps = 16 bt rows.
// Phase 1: w_par chunked+TRANSPOSED in smem; each lane computes 2
// adjacent params via f32x2 (acc.lo/acc.hi), te broadcast-LDS.
// Registers bounded by construction (no per-thread w caches).
// ------------------------------------------------------------------
#define PAIRS 16
#define WT_PITCH 130                       // words; even => 8B-aligned LDS.64
#define SM_TE    (PAIRS * 32 * 8)          // te dup'd as f32x2      4096 B
#define SM_WT    (32 * WT_PITCH * 4)       // transposed w chunk    16640 B
#define SM_PS    (PAIRS * NPARD * 4)       // params               67584 B
#define SM_ST    (PAIRS * 48 * 4)          // states                3072 B
#define SM_HID   (PAIRS * 16 * 4)          //                       1024 B
#define TAIL_SMEM (SM_TE + SM_WT + SM_PS + SM_ST + SM_HID)

__global__ __launch_bounds__(512, 2) void k_tail(const float* __restrict__ x,
                                                 const float* __restrict__ w_par,
                                                 const float* __restrict__ b_par,
                                                 float* __restrict__ out_mean,
                                                 float* __restrict__ out_std)
{
    extern __shared__ char smem[];
    ull*   te2 = (ull*)smem;                       // [16][32] (dup'd)
    float* wt  = (float*)(smem + SM_TE);           // [32][WT_PITCH]
    float* ps  = (float*)(smem + SM_TE + SM_WT);   // [16][1056]
    float* st_s= (float*)(smem + SM_TE + SM_WT + SM_PS);   // [16][48]
    float* hid = st_s + PAIRS * 48;                // [16][16]

    int tid = threadIdx.x;
    int lane = tid & 31;
    int wrp  = tid >> 5;            // pair index
    int bt0 = blockIdx.x * PAIRS;

    // load task_enc, duplicated into both f32x2 halves (exactly 512 elems)
    {
        int p = tid >> 5, l = tid & 31;
        float v = g_te[(size_t)(bt0 + p) * LD + l];
        unsigned u = __float_as_uint(v);
        te2[p * 32 + l] = ((ull)u << 32) | u;
    }
    if (tid < PAIRS * 12) {
        int p = tid / 12, c = tid % 12;
        ((float4*)&st_s[p * 48])[c] = ((const float4*)x)[(size_t)(bt0 + p) * 16 + c];
    }

    const ull* myte = &te2[wrp * 32];

    // phase 1: params over 8 full chunks of 128 idx + one 32-idx tail
    #pragma unroll 1
    for (int c = 0; c < 9; c++) {
        int idx0 = c * 128;
        int nc = (c < 8) ? 128 : 32;
        __syncthreads();
        // stage chunk transposed: wt[k][i] = w_par[idx0+i][k]
        for (int q = tid; q < nc * 8; q += 512) {
            int i = q >> 3, c4 = q & 7;
            float4 v = ((const float4*)w_par)[(size_t)(idx0 + i) * 8 + c4];
            wt[(c4*4+0) * WT_PITCH + i] = v.x;
            wt[(c4*4+1) * WT_PITCH + i] = v.y;
            wt[(c4*4+2) * WT_PITCH + i] = v.z;
            wt[(c4*4+3) * WT_PITCH + i] = v.w;
        }
        __syncthreads();
        // each lane: idx pairs (2*lane) and (2*lane+64) [full chunks]
        #pragma unroll
        for (int half = 0; half < 2; half++) {
            int ip = 2 * lane + half * 64;
            if (ip < nc) {
                ull acc = 0ull;
                #pragma unroll
                for (int k = 0; k < 32; k++)
                    acc = fma2(*(const ull*)&wt[k * WT_PITCH + ip], myte[k], acc);
                ull bb = *(const ull*)&b_par[idx0 + ip];
                *(ull*)&ps[wrp * NPARD + idx0 + ip] = add2(acc, bb);
            }
        }
    }
    __syncthreads();

    // phase 2: out_hidden[pair][p] = tanh(w_h[p,:] . state + b_h[p])
    if (tid < PAIRS * 16) {
        int pair = tid >> 4, p = tid & 15;
        const float4* wh4 = (const float4*)(ps + pair * NPARD + p * 48);
        const float4* st4 = (const float4*)&st_s[pair * 48];
        float a = ps[pair * NPARD + 768 + p];
        #pragma unroll
        for (int q = 0; q < 12; q++) {
            float4 wv = wh4[q];
            float4 sv = st4[q];
            a = fmaf(wv.x, sv.x, a); a = fmaf(wv.y, sv.y, a);
            a = fmaf(wv.z, sv.z, a); a = fmaf(wv.w, sv.w, a);
        }
        hid[pair * 16 + p] = tanhf(a);
    }
    __syncthreads();

    // phase 3: mlp[pair][o] = w_o[o,:] . hidden + b_o[o]
    if (tid < PAIRS * 16) {
        int pair = tid >> 4, o = tid & 15;
        const float4* wo4 = (const float4*)(ps + pair * NPARD + 784 + o * 16);
        const float4* hv4 = (const float4*)&hid[pair * 16];
        float m = ps[pair * NPARD + 1040 + o];
        #pragma unroll
        for (int q = 0; q < 4; q++) {
            float4 wv = wo4[q];
            float4 hv = hv4[q];
            m = fmaf(wv.x, hv.x, m); m = fmaf(wv.y, hv.y, m);
            m = fmaf(wv.z, hv.z, m); m = fmaf(wv.w, hv.w, m);
        }
        size_t bt = bt0 + pair;
        if (o < 8) out_mean[bt * ODD + o] = m;
        else       out_std[bt * ODD + (o - 8)] = expf(m);
    }
}

// ------------------------------------------------------------------
extern "C" void kernel_launch(void* const* d_in, const int* in_sizes, int n_in,
                              void* d_out, int out_size)
{
    const float* x      = (const float*)d_in[0];
    const float* hidden = (const float*)d_in[1];
    const float* w_ih   = (const float*)d_in[2];
    const float* w_hh   = (const float*)d_in[3];
    const float* b_ih   = (const float*)d_in[4];
    const float* b_hh   = (const float*)d_in[5];
    const float* w_lat  = (const float*)d_in[6];
    const float* b_lat  = (const float*)d_in[7];
    const float* w_par  = (const float*)d_in[8];
    const float* b_par  = (const float*)d_in[9];
    (void)in_sizes; (void)n_in; (void)out_size;

    float* out      = (float*)d_out;
    float* out_mean = out;                                  // B*T*8
    float* out_std  = out + (size_t)BB * TT * ODD;          // B*T*8
    float* out_hT   = out + (size_t)2 * BB * TT * ODD;      // B*256

    cudaFuncSetAttribute(k_tail, cudaFuncAttributeMaxDynamicSharedMemorySize, TAIL_SMEM);

    dim3 g1(G3 / 64, (BB * TT) / 64), b1(16, 16);
    k_gx  <<<g1, b1>>>(x, w_ih, b_ih);
    k_gru <<<(BB / NBAT) * CL, G3>>>(hidden, w_hh, b_hh, out_hT);
    k_te  <<<(BB * TT) / 32, 256>>>(w_lat, b_lat);
    k_tail<<<(BB * TT) / PAIRS, 512, TAIL_SMEM>>>(x, w_par, b_par, out_mean, out_std);
}

// round 10
// speedup vs baseline: 1.5984x; 1.1005x over previous
#include <cuda_runtime.h>
#include <math.h>

typedef unsigned long long ull;

#define BB 128
#define TT 512
#define IND 64
#define HD 256
#define G3 768
#define LD 32
#define NPARD 1056
#define ODD 8

#define CL 4            // cluster size (K split of hidden dim)
#define NBAT 4          // batches per cluster
#define KS (HD/CL)      // 64 K-columns per CTA

// Scratch (static device arrays — no allocation allowed)
__device__ float g_gx[BB*TT*G3];    // 192 MB
__device__ float g_rnn[BB*TT*HD];   // 64 MB
__device__ float g_te[BB*TT*LD];    // 8 MB

__device__ __forceinline__ float sigm(float x){ return 1.0f/(1.0f+expf(-x)); }

// packed fp32 ops (Blackwell f32x2)
__device__ __forceinline__ ull fma2(ull a, ull b, ull c){
    ull d;
    asm("fma.rn.f32x2 %0, %1, %2, %3;" : "=l"(d) : "l"(a), "l"(b), "l"(c));
    return d;
}
__device__ __forceinline__ ull add2(ull a, ull b){
    ull d;
    asm("add.rn.f32x2 %0, %1, %2;" : "=l"(d) : "l"(a), "l"(b));
    return d;
}
__device__ __forceinline__ float hadd2(ull a){
    unsigned lo, hi;
    asm("mov.b64 {%0,%1}, %2;" : "=r"(lo), "=r"(hi) : "l"(a));
    return __uint_as_float(lo) + __uint_as_float(hi);
}

// ------------------------------------------------------------------
// K1: gx[bt,g] = x[bt,:] . w_ih[g,:] + b_ih[g]   (f32x2 microkernel)
// ------------------------------------------------------------------
__global__ __launch_bounds__(256) void k_gx(const float* __restrict__ x,
                                            const float* __restrict__ w_ih,
                                            const float* __restrict__ b_ih)
{
    __shared__ float2 xs[64][33];
    __shared__ float2 ws[64][33];
    int m0 = blockIdx.y * 64;
    int n0 = blockIdx.x * 64;
    int tid = threadIdx.y * 16 + threadIdx.x;
    const float4* x4 = (const float4*)x;
    const float4* w4 = (const float4*)w_ih;
    for (int q = tid; q < 1024; q += 256) {
        int row = q >> 4, c4 = q & 15;
        float4 v = x4[(size_t)(m0 + row) * 16 + c4];
        xs[row][c4*2+0] = make_float2(v.x, v.y);
        xs[row][c4*2+1] = make_float2(v.z, v.w);
        float4 wv = w4[(size_t)(n0 + row) * 16 + c4];
        ws[row][c4*2+0] = make_float2(wv.x, wv.y);
        ws[row][c4*2+1] = make_float2(wv.z, wv.w);
    }
    __syncthreads();
    int tr = threadIdx.y * 4, tc = threadIdx.x * 4;
    ull acc[4][4] = {};
    #pragma unroll 8
    for (int k2 = 0; k2 < 32; k2++) {
        ull av[4], bv[4];
        #pragma unroll
        for (int i = 0; i < 4; i++) av[i] = *(const ull*)&xs[tr + i][k2];
        #pragma unroll
        for (int j = 0; j < 4; j++) bv[j] = *(const ull*)&ws[tc + j][k2];
        #pragma unroll
        for (int i = 0; i < 4; i++)
            #pragma unroll
            for (int j = 0; j < 4; j++)
                acc[i][j] = fma2(av[i], bv[j], acc[i][j]);
    }
    float b0 = b_ih[n0+tc+0], b1 = b_ih[n0+tc+1], b2 = b_ih[n0+tc+2], b3 = b_ih[n0+tc+3];
    #pragma unroll
    for (int i = 0; i < 4; i++) {
        float4 o;
        o.x = hadd2(acc[i][0]) + b0; o.y = hadd2(acc[i][1]) + b1;
        o.z = hadd2(acc[i][2]) + b2; o.w = hadd2(acc[i][3]) + b3;
        *(float4*)&g_gx[(size_t)(m0 + tr + i) * G3 + n0 + tc] = o;
    }
}

// ------------------------------------------------------------------
// K2: GRU recurrence (best measured): cluster of 4 CTAs, w_hh in
// registers, f32x2 FMA, h via LDS.128.  (UNCHANGED from R9)
// ------------------------------------------------------------------
__global__ __launch_bounds__(G3, 1) __cluster_dims__(CL, 1, 1)
void k_gru(const float* __restrict__ hidden,
           const float* __restrict__ w_hh,
           const float* __restrict__ b_hh,
           float* __restrict__ hT)
{
    __shared__ float4 hs4[NBAT][KS/4];          // local hidden slice, 4 x 64
    __shared__ float pbuf[2][CL][NBAT][192];    // partial sums, double-buffered
    int tid = threadIdx.x;
    unsigned rank;
    asm("mov.u32 %0, %%cluster_ctarank;" : "=r"(rank));
    int b0 = (blockIdx.x / CL) * NBAT;

    float4 w[KS/4];
    {
        const float4* wsrc = (const float4*)(w_hh + (size_t)tid * HD + KS * rank);
        #pragma unroll
        for (int i = 0; i < KS/4; i++) w[i] = wsrc[i];
    }

    float* hs = (float*)hs4;
    int gb = tid >> 6, gj = tid & 63;
    int hidx = KS * (int)rank + gj;
    float bh_r = 0.f, bh_z = 0.f, bh_n = 0.f;
    if (tid < NBAT * KS) {
        hs[gb * KS + gj] = hidden[(size_t)(b0 + gb) * HD + hidx];
        bh_r = b_hh[hidx]; bh_z = b_hh[HD + hidx]; bh_n = b_hh[2*HD + hidx];
    }

    int dest = (tid & 255) >> 6;
    int slot = (tid >> 8) * 64 + (tid & 63);
    unsigned raddr0, raddr1;
    {
        unsigned la0 = (unsigned)__cvta_generic_to_shared(&pbuf[0][rank][0][slot]);
        unsigned la1 = (unsigned)__cvta_generic_to_shared(&pbuf[1][rank][0][slot]);
        asm("mapa.shared::cluster.u32 %0, %1, %2;" : "=r"(raddr0) : "r"(la0), "r"(dest));
        asm("mapa.shared::cluster.u32 %0, %1, %2;" : "=r"(raddr1) : "r"(la1), "r"(dest));
    }
    __syncthreads();

    for (int t = 0; t < TT; t++) {
        float xr = 0.f, xz = 0.f, xn = 0.f;
        if (tid < NBAT * KS) {
            const float* gxp = g_gx + ((size_t)(b0 + gb) * TT + t) * G3;
            xr = gxp[hidx]; xz = gxp[HD + hidx]; xn = gxp[2*HD + hidx];
        }
        ull a0 = 0ull, a1 = 0ull, a2 = 0ull, a3 = 0ull;
        #pragma unroll
        for (int k = 0; k < KS/4; k++) {
            float4 wv = w[k];
            ull w01 = *(const ull*)&wv.x;
            ull w23 = *(const ull*)&wv.z;
            float4 h0 = hs4[0][k];
            a0 = fma2(w01, *(const ull*)&h0.x, a0);
            a0 = fma2(w23, *(const ull*)&h0.z, a0);
            float4 h1 = hs4[1][k];
            a1 = fma2(w01, *(const ull*)&h1.x, a1);
            a1 = fma2(w23, *(const ull*)&h1.z, a1);
            float4 h2 = hs4[2][k];
            a2 = fma2(w01, *(const ull*)&h2.x, a2);
            a2 = fma2(w23, *(const ull*)&h2.z, a2);
            float4 h3 = hs4[3][k];
            a3 = fma2(w01, *(const ull*)&h3.x, a3);
            a3 = fma2(w23, *(const ull*)&h3.z, a3);
        }
        float s0 = hadd2(a0), s1 = hadd2(a1), s2 = hadd2(a2), s3 = hadd2(a3);

        unsigned ra = (t & 1) ? raddr1 : raddr0;
        asm volatile("st.shared::cluster.f32 [%0], %1;" :: "r"(ra),         "f"(s0));
        asm volatile("st.shared::cluster.f32 [%0], %1;" :: "r"(ra + 768u),  "f"(s1));
        asm volatile("st.shared::cluster.f32 [%0], %1;" :: "r"(ra + 1536u), "f"(s2));
        asm volatile("st.shared::cluster.f32 [%0], %1;" :: "r"(ra + 2304u), "f"(s3));
        asm volatile("barrier.cluster.arrive.aligned;" ::: "memory");
        asm volatile("barrier.cluster.wait.aligned;"   ::: "memory");

        if (tid < NBAT * KS) {
            int buf = t & 1;
            float hr = pbuf[buf][0][gb][gj]     + pbuf[buf][1][gb][gj]
                     + pbuf[buf][2][gb][gj]     + pbuf[buf][3][gb][gj]     + bh_r;
            float hz = pbuf[buf][0][gb][64+gj]  + pbuf[buf][1][gb][64+gj]
                     + pbuf[buf][2][gb][64+gj]  + pbuf[buf][3][gb][64+gj]  + bh_z;
            float hn = pbuf[buf][0][gb][128+gj] + pbuf[buf][1][gb][128+gj]
                     + pbuf[buf][2][gb][128+gj] + pbuf[buf][3][gb][128+gj] + bh_n;
            float r = sigm(xr + hr);
            float z = sigm(xz + hz);
            float n = tanhf(xn + r * hn);
            float hp = hs[gb*KS + gj];
            float hnew = (1.0f - z) * n + z * hp;
            hs[gb*KS + gj] = hnew;
            g_rnn[((size_t)(b0 + gb) * TT + t) * HD + hidx] = hnew;
        }
        __syncthreads();
    }
    if (tid < NBAT * KS) hT[(size_t)(b0 + gb) * HD + hidx] = hs[gb*KS + gj];
}

// ------------------------------------------------------------------
// K3a: task_enc[bt,l] = rnn[bt,:] . w_lat[l,:] + b_lat[l]  (f32x2)
// ------------------------------------------------------------------
__global__ __launch_bounds__(256) void k_te(const float* __restrict__ w_lat,
                                            const float* __restrict__ b_lat)
{
    __shared__ ulonglong2 rows4[32 * 64];
    int tid = threadIdx.x;
    int bt0 = blockIdx.x * 32;
    const ulonglong2* rnn4 = (const ulonglong2*)g_rnn;
    for (int q = tid; q < 2048; q += 256) rows4[q] = rnn4[(size_t)bt0 * 64 + q];
    __syncthreads();
    int pair = tid >> 3;
    int l0 = (tid & 7) * 4;
    const ulonglong2* wl4 = (const ulonglong2*)w_lat;
    ull acc[4] = {};
    #pragma unroll 8
    for (int k4 = 0; k4 < 64; k4++) {
        ulonglong2 r = rows4[pair * 64 + k4];
        #pragma unroll
        for (int j = 0; j < 4; j++) {
            ulonglong2 wv = wl4[(size_t)(l0 + j) * 64 + k4];
            acc[j] = fma2(r.x, wv.x, acc[j]);
            acc[j] = fma2(r.y, wv.y, acc[j]);
        }
    }
    float4 o;
    o.x = hadd2(acc[0]) + b_lat[l0+0];
    o.y = hadd2(acc[1]) + b_lat[l0+1];
    o.z = hadd2(acc[2]) + b_lat[l0+2];
    o.w = hadd2(acc[3]) + b_lat[l0+3];
    *(float4*)&g_te[(size_t)(bt0 + pair) * LD + l0] = o;
}

// ------------------------------------------------------------------
// K3b: fused tail v3 — register-microtiled phase-1 GEMM.
// 1024 threads, 32 bt/block. w_par staged transposed in 512-idx
// chunks; thread tile = 2 idx-pairs x 4 bt  => 6 B smem / fma2.
// ------------------------------------------------------------------
#define PAIRS 32
#define WT_PITCH 514                       // words; 8B-aligned rows, de-conflicted staging
#define SM_TE    (PAIRS * 32 * 8)          // te dup'd as f32x2      8192 B
#define SM_WT    (32 * WT_PITCH * 4)       // transposed w chunk    65792 B
#define SM_PS    (PAIRS * NPARD * 4)       // params              135168 B
#define SM_ST    (PAIRS * 48 * 4)          // states                6144 B
#define SM_HID   (PAIRS * 16 * 4)          //                       2048 B
#define TAIL_SMEM (SM_TE + SM_WT + SM_PS + SM_ST + SM_HID)   // 217344 B

__global__ __launch_bounds__(1024, 1) void k_tail(const float* __restrict__ x,
                                                  const float* __restrict__ w_par,
                                                  const float* __restrict__ b_par,
                                                  float* __restrict__ out_mean,
                                                  float* __restrict__ out_std)
{
    extern __shared__ char smem[];
    ull*   te2 = (ull*)smem;                       // [32][32] (dup'd halves)
    float* wt  = (float*)(smem + SM_TE);           // [32][WT_PITCH]
    float* ps  = (float*)(smem + SM_TE + SM_WT);   // [32][1056]
    float* st_s= (float*)(smem + SM_TE + SM_WT + SM_PS);   // [32][48]
    float* hid = st_s + PAIRS * 48;                // [32][16]

    int tid = threadIdx.x;
    int bt0 = blockIdx.x * PAIRS;

    // load task_enc, duplicated into both f32x2 halves (exactly 1024 elems)
    {
        int p = tid >> 5, l = tid & 31;
        float v = g_te[(size_t)(bt0 + p) * LD + l];
        unsigned u = __float_as_uint(v);
        te2[p * 32 + l] = ((ull)u << 32) | u;
    }
    if (tid < PAIRS * 12) {
        int p = tid / 12, c = tid % 12;
        ((float4*)&st_s[p * 48])[c] = ((const float4*)x)[(size_t)(bt0 + p) * 16 + c];
    }

    // thread tile: pairs {pt, pt+128} x bts {4*btile .. 4*btile+3}
    int pt    = tid & 127;
    int btile = tid >> 7;        // 0..7
    const ull* myte = &te2[(btile * 4) * 32];

    // ---- phase 1: two full 512-idx passes ----
    #pragma unroll 1
    for (int pass = 0; pass < 2; pass++) {
        int idx0 = pass * 512;
        __syncthreads();
        // stage chunk transposed: wt[k][i] = w_par[idx0+i][k]
        #pragma unroll 1
        for (int q = tid; q < 512 * 8; q += 1024) {
            int i = q >> 3, c4 = q & 7;
            float4 v = ((const float4*)w_par)[(size_t)(idx0 + i) * 8 + c4];
            wt[(c4*4+0) * WT_PITCH + i] = v.x;
            wt[(c4*4+1) * WT_PITCH + i] = v.y;
            wt[(c4*4+2) * WT_PITCH + i] = v.z;
            wt[(c4*4+3) * WT_PITCH + i] = v.w;
        }
        __syncthreads();

        ull acc0[4] = {}, acc1[4] = {};
        #pragma unroll
        for (int k = 0; k < 32; k++) {
            ull wa = *(const ull*)&wt[k * WT_PITCH + 2 * pt];
            ull wb = *(const ull*)&wt[k * WT_PITCH + 2 * pt + 256];
            #pragma unroll
            for (int b = 0; b < 4; b++) {
                ull tv = myte[b * 32 + k];
                acc0[b] = fma2(wa, tv, acc0[b]);
                acc1[b] = fma2(wb, tv, acc1[b]);
            }
        }
        int idxA = idx0 + 2 * pt;
        int idxB = idx0 + 2 * pt + 256;
        ull bbA = *(const ull*)&b_par[idxA];
        ull bbB = *(const ull*)&b_par[idxB];
        #pragma unroll
        for (int b = 0; b < 4; b++) {
            int bt = btile * 4 + b;
            *(ull*)&ps[bt * NPARD + idxA] = add2(acc0[b], bbA);
            *(ull*)&ps[bt * NPARD + idxB] = add2(acc1[b], bbB);
        }
    }

    // ---- phase 1 tail: idx 1024..1055 (16 pairs x 32 bt) ----
    __syncthreads();
    #pragma unroll 1
    for (int q = tid; q < 32 * 8; q += 1024) {
        int i = q >> 3, c4 = q & 7;
        float4 v = ((const float4*)w_par)[(size_t)(1024 + i) * 8 + c4];
        wt[(c4*4+0) * WT_PITCH + i] = v.x;
        wt[(c4*4+1) * WT_PITCH + i] = v.y;
        wt[(c4*4+2) * WT_PITCH + i] = v.z;
        wt[(c4*4+3) * WT_PITCH + i] = v.w;
    }
    __syncthreads();
    if (tid < 512) {
        int p2 = tid & 15;            // pair 0..15
        int bt = tid >> 4;            // 0..31
        const ull* bte = &te2[bt * 32];
        ull acc = 0ull;
        #pragma unroll
        for (int k = 0; k < 32; k++)
            acc = fma2(*(const ull*)&wt[k * WT_PITCH + 2 * p2], bte[k], acc);
        int idx = 1024 + 2 * p2;
        ull bb = *(const ull*)&b_par[idx];
        *(ull*)&ps[bt * NPARD + idx] = add2(acc, bb);
    }
    __syncthreads();

    // ---- phase 2: out_hidden[pair][p] = tanh(w_h[p,:] . state + b_h[p]) ----
    if (tid < PAIRS * 16) {
        int pair = tid >> 4, p = tid & 15;
        const float4* wh4 = (const float4*)(ps + pair * NPARD + p * 48);
        const float4* st4 = (const float4*)&st_s[pair * 48];
        float a = ps[pair * NPARD + 768 + p];
        #pragma unroll
        for (int q = 0; q < 12; q++) {
            float4 wv = wh4[q];
            float4 sv = st4[q];
            a = fmaf(wv.x, sv.x, a); a = fmaf(wv.y, sv.y, a);
            a = fmaf(wv.z, sv.z, a); a = fmaf(wv.w, sv.w, a);
        }
        hid[pair * 16 + p] = tanhf(a);
    }
    __syncthreads();

    // ---- phase 3: mlp[pair][o] = w_o[o,:] . hidden + b_o[o] ----
    if (tid < PAIRS * 16) {
        int pair = tid >> 4, o = tid & 15;
        const float4* wo4 = (const float4*)(ps + pair * NPARD + 784 + o * 16);
        const float4* hv4 = (const float4*)&hid[pair * 16];
        float m = ps[pair * NPARD + 1040 + o];
        #pragma unroll
        for (int q = 0; q < 4; q++) {
            float4 wv = wo4[q];
            float4 hv = hv4[q];
            m = fmaf(wv.x, hv.x, m); m = fmaf(wv.y, hv.y, m);
            m = fmaf(wv.z, hv.z, m); m = fmaf(wv.w, hv.w, m);
        }
        size_t bt = bt0 + pair;
        if (o < 8) out_mean[bt * ODD + o] = m;
        else       out_std[bt * ODD + (o - 8)] = expf(m);
    }
}

// ------------------------------------------------------------------
extern "C" void kernel_launch(void* const* d_in, const int* in_sizes, int n_in,
                              void* d_out, int out_size)
{
    const float* x      = (const float*)d_in[0];
    const float* hidden = (const float*)d_in[1];
    const float* w_ih   = (const float*)d_in[2];
    const float* w_hh   = (const float*)d_in[3];
    const float* b_ih   = (const float*)d_in[4];
    const float* b_hh   = (const float*)d_in[5];
    const float* w_lat  = (const float*)d_in[6];
    const float* b_lat  = (const float*)d_in[7];
    const float* w_par  = (const float*)d_in[8];
    const float* b_par  = (const float*)d_in[9];
    (void)in_sizes; (void)n_in; (void)out_size;

    float* out      = (float*)d_out;
    float* out_mean = out;                                  // B*T*8
    float* out_std  = out + (size_t)BB * TT * ODD;          // B*T*8
    float* out_hT   = out + (size_t)2 * BB * TT * ODD;      // B*256

    cudaFuncSetAttribute(k_tail, cudaFuncAttributeMaxDynamicSharedMemorySize, TAIL_SMEM);

    dim3 g1(G3 / 64, (BB * TT) / 64), b1(16, 16);
    k_gx  <<<g1, b1>>>(x, w_ih, b_ih);
    k_gru <<<(BB / NBAT) * CL, G3>>>(hidden, w_hh, b_hh, out_hT);
    k_te  <<<(BB * TT) / 32, 256>>>(w_lat, b_lat);
    k_tail<<<(BB * TT) / PAIRS, 1024, TAIL_SMEM>>>(x, w_par, b_par, out_mean, out_std);
}